// round 14
// baseline (speedup 1.0000x reference)
#include <cuda_runtime.h>
#include <cuda_fp16.h>
#include <cstdint>

#define HID  256
#define NPTS 270336               // 262144 eq + 8192 boundary

// ---------------------------------------------------------------------------
// Static device scratch
// state[gen][stream v/d1/d2][hi=0,lo=1][pt][k]
__device__ __half g_state[2][3][2][NPTS][HID];
// transposed split weights: wt[layer][img][j][k] = split(W[k][j])
__device__ __half g_wt[3][2][HID][HID];
// z' f32 scratch (written stream-1 epilogue, read stream-2 epilogue by same thread)
__device__ float g_z1[(size_t)NPTS * HID];

// ---------------------------------------------------------------------------
// 32-byte-row swizzle: XOR bit4 (16B unit) with bit7 (row bit 2).
// Conflict-free for 8-row ldsm phases; bijective on 16B units.
#define SWZ32(o) ((uint32_t)(o) ^ ((((uint32_t)(o)) >> 3) & 0x10))

__device__ __forceinline__ uint32_t smem_u32(const void* p) {
    uint32_t a;
    asm("{ .reg .u64 t; cvta.to.shared.u64 t, %1; cvt.u32.u64 %0, t; }"
        : "=r"(a) : "l"(p));
    return a;
}
__device__ __forceinline__ void ldsm4(uint32_t* r, uint32_t a) {
    asm volatile("ldmatrix.sync.aligned.m8n8.x4.shared.b16 {%0,%1,%2,%3}, [%4];"
                 : "=r"(r[0]), "=r"(r[1]), "=r"(r[2]), "=r"(r[3]) : "r"(a));
}
__device__ __forceinline__ void mma_f16(float* c, const uint32_t* a,
                                        uint32_t b0, uint32_t b1) {
    asm volatile(
        "mma.sync.aligned.m16n8k16.row.col.f32.f16.f16.f32 "
        "{%0,%1,%2,%3}, {%4,%5,%6,%7}, {%8,%9}, {%0,%1,%2,%3};"
        : "+f"(c[0]), "+f"(c[1]), "+f"(c[2]), "+f"(c[3])
        : "r"(a[0]), "r"(a[1]), "r"(a[2]), "r"(a[3]), "r"(b0), "r"(b1));
}
#define CP16(dst, src) \
    asm volatile("cp.async.cg.shared.global [%0], [%1], 16;" \
                 :: "r"(dst), "l"(src) : "memory")
#define CP_COMMIT() asm volatile("cp.async.commit_group;" ::: "memory")
#define CP_WAIT1()  asm volatile("cp.async.wait_group 1;" ::: "memory")
#define CP_WAIT0()  asm volatile("cp.async.wait_group 0;" ::: "memory")

__device__ __forceinline__ void split_h(float v, __half& hi, __half& lo) {
    hi = __float2half_rn(v);
    lo = __float2half_rn(v - __half2float(hi));
}
__device__ __forceinline__ uint32_t pack_h(__half a, __half b) {
    return (uint32_t)__half_as_ushort(a) | ((uint32_t)__half_as_ushort(b) << 16);
}
__device__ __forceinline__ float h_lo(uint32_t u) {
    return __half2float(__ushort_as_half((unsigned short)(u & 0xFFFF)));
}
__device__ __forceinline__ float h_hi(uint32_t u) {
    return __half2float(__ushort_as_half((unsigned short)(u >> 16)));
}

// ---------------------------------------------------------------------------
__global__ void prep_kernel(const float* __restrict__ W1,
                            const float* __restrict__ W2,
                            const float* __restrict__ W3) {
    const float* Ws[3] = {W1, W2, W3};
    int idx = blockIdx.x * 256 + threadIdx.x;   // < 196608
    int l = idx >> 16, r = idx & 0xFFFF;
    int j = r >> 8, k = r & 255;
    __half hi, lo;
    split_h(Ws[l][k * HID + j], hi, lo);
    g_wt[l][0][j][k] = hi;
    g_wt[l][1][j][k] = lo;
}

__global__ void layer0_kernel(const float* __restrict__ xe,
                              const float* __restrict__ xb,
                              const float* __restrict__ W0,
                              const float* __restrict__ b0, int n_eq) {
    int tid = threadIdx.x, wid = tid >> 5, lane = tid & 31;
    int pt = blockIdx.x * 8 + wid;
    bool eq = pt < n_eq;
    float xv = eq ? xe[pt] : xb[pt - n_eq];
    int j0 = lane * 8;
    __half vh[8], vl[8], ah[8], al[8], bh[8], bl[8];
#pragma unroll
    for (int i = 0; i < 8; ++i) {
        float w = W0[j0 + i];
        float z = fmaf(xv, w, b0[j0 + i]);
        float a = tanhf(z);
        float sf = 1.0f - a * a;
        float d1 = eq ? sf * w : 0.0f;
        float d2 = eq ? (-2.0f * a * sf * w * w) : 0.0f;
        split_h(a,  vh[i], vl[i]);
        split_h(d1, ah[i], al[i]);
        split_h(d2, bh[i], bl[i]);
    }
    size_t off = (size_t)pt * HID + j0;
    *(uint4*)(&g_state[0][0][0][0][0] + off) = *(uint4*)vh;
    *(uint4*)(&g_state[0][0][1][0][0] + off) = *(uint4*)vl;
    *(uint4*)(&g_state[0][1][0][0][0] + off) = *(uint4*)ah;
    *(uint4*)(&g_state[0][1][1][0][0] + off) = *(uint4*)al;
    *(uint4*)(&g_state[0][2][0][0][0] + off) = *(uint4*)bh;
    *(uint4*)(&g_state[0][2][1][0][0] + off) = *(uint4*)bl;
}

// ---------------------------------------------------------------------------
// hidden layer: CTA = 64 pts x 256 N (full N), 256 threads, 2 CTAs/SM.
// 8 warps in 2(m) x 4(n), warp tile 32x64.
// kc=16: buffer = A 2img x [64][16] (4KB) + B 2img x [256][16] (16KB) = 20KB,
// 3 buffers, depth-2 cp.async, 1 barrier/chunk. it = s*16 + c.
// B frags loaded twice per chunk into the same regs (hi then lo).
// ---------------------------------------------------------------------------
#define BUFB       20480
#define SM_buf(b)  ((b) * BUFB)
#define SM_BIAS    61440
#define SMEM_HK    62464
#define NITER      48
#define THD        256

__global__ void __launch_bounds__(THD, 2)
hidden_kernel(int gin, int gout, int lw, const float* __restrict__ bias)
{
    extern __shared__ char sm[];
    const uint32_t sb = smem_u32(sm);
    float* bs = (float*)(sm + SM_BIAS);
    const int tid = threadIdx.x, lane = tid & 31, wid = tid >> 5;
    const int wm = wid >> 2, wn = wid & 3;        // warp grid 2(m) x 4(n)
    const int pt0 = blockIdx.x * 64;

    bs[tid] = bias[tid];

    const __half* wbase = &g_wt[lw][0][0][0];
    const __half* sbase = &g_state[gin][0][0][0][0];     // stream stride 2*NPTS*HID
    __half* outb = &g_state[gout][0][0][0][0];
    const size_t IS = (size_t)NPTS * HID;                // img stride
    const size_t SS = 2 * IS;                            // stream stride

    // ---- thread-constant staging offsets ----
    // A: 256 16B-units (2 img x 64 rows x 2), B: 1024 (2 img x 256 rows x 2)
    uint32_t a_dst; size_t a_src;
    uint32_t b_dst[4]; size_t b_src[4];
    {
        int img = tid >> 7, u = tid & 127, row = u >> 1, k8 = u & 1;
        a_dst = img * 2048 + SWZ32(row * 32 + k8 * 16);
        a_src = (size_t)img * IS + (size_t)(pt0 + row) * HID + k8 * 8;
    }
#pragma unroll
    for (int i = 0; i < 4; ++i) {
        int idx = tid + i * THD;
        int img = idx >> 9, u = idx & 511, row = u >> 1, k8 = u & 1;
        b_dst[i] = 4096 + img * 8192 + SWZ32(row * 32 + k8 * 16);
        b_src[i] = (size_t)img * HID * HID + (size_t)row * HID + k8 * 8;
    }

    auto stage = [&](int it) {
        const int s = it >> 4, c = it & 15;
        const __half* ab = sbase + (size_t)s * SS + c * 16;
        const __half* bb = wbase + c * 16;
        const uint32_t buf = sb + SM_buf(it % 3);
        CP16(buf + a_dst, ab + a_src);
#pragma unroll
        for (int i = 0; i < 4; ++i) CP16(buf + b_dst[i], bb + b_src[i]);
        CP_COMMIT();
    };

    float acc[2][8][4];
    stage(0);
    stage(1);

    // ---- hoisted ldsm offsets (full swizzle per row, exact) ----
    const uint32_t klane = (lane >> 4) << 4;
    const int rA = wm * 32 + (lane & 15);
    const int rB = wn * 64 + (lane & 15);
    uint32_t aoff[2], boff[4];
#pragma unroll
    for (int mi = 0; mi < 2; ++mi)
        aoff[mi] = SWZ32((uint32_t)((rA + mi * 16) * 32) + klane);
#pragma unroll
    for (int g = 0; g < 4; ++g)
        boff[g] = SWZ32((uint32_t)((rB + g * 16) * 32) + klane);

    for (int it = 0; it < NITER; ++it) {
        const int s = it >> 4, c = it & 15;

        if (c == 0) {
#pragma unroll
            for (int mi = 0; mi < 2; ++mi)
#pragma unroll
                for (int nj = 0; nj < 8; ++nj)
#pragma unroll
                    for (int q = 0; q < 4; ++q) acc[mi][nj][q] = 0.0f;
        }

        if (it + 2 < NITER) CP_WAIT1();
        else                CP_WAIT0();
        __syncthreads();                 // chunk(it) visible; compute(it-1) done
        if (it + 2 < NITER) stage(it + 2);

        const uint32_t abuf = sb + SM_buf(it % 3);
        const uint32_t bbuf = abuf + 4096;

        uint32_t ah[2][4], al[2][4], bf[4][4];
#pragma unroll
        for (int mi = 0; mi < 2; ++mi) {
            ldsm4(ah[mi], abuf + aoff[mi]);
            ldsm4(al[mi], abuf + 2048 + aoff[mi]);
        }
        // ---- B-hi frags: passes (ah·bh) and (al·bh) ----
#pragma unroll
        for (int g = 0; g < 4; ++g) ldsm4(bf[g], bbuf + boff[g]);
#pragma unroll
        for (int mi = 0; mi < 2; ++mi)
#pragma unroll
            for (int g = 0; g < 4; ++g) {
                mma_f16(acc[mi][2*g],   ah[mi], bf[g][0], bf[g][2]);
                mma_f16(acc[mi][2*g+1], ah[mi], bf[g][1], bf[g][3]);
            }
#pragma unroll
        for (int mi = 0; mi < 2; ++mi)
#pragma unroll
            for (int g = 0; g < 4; ++g) {
                mma_f16(acc[mi][2*g],   al[mi], bf[g][0], bf[g][2]);
                mma_f16(acc[mi][2*g+1], al[mi], bf[g][1], bf[g][3]);
            }
        // ---- B-lo frags (reuse regs): pass (ah·bl) ----
#pragma unroll
        for (int g = 0; g < 4; ++g) ldsm4(bf[g], bbuf + 8192 + boff[g]);
#pragma unroll
        for (int mi = 0; mi < 2; ++mi)
#pragma unroll
            for (int g = 0; g < 4; ++g) {
                mma_f16(acc[mi][2*g],   ah[mi], bf[g][0], bf[g][2]);
                mma_f16(acc[mi][2*g+1], ah[mi], bf[g][1], bf[g][3]);
            }

        if (c == 15) {
            // ---- epilogue: c frag rows lane>>2 +{0,8}; cols (lane&3)*2 +{0,1} ----
            const int mr  = pt0 + wm * 32 + (lane >> 2);
            const int nc0 = wn * 64 + (lane & 3) * 2;
            __half* pv_h = outb;          __half* pv_l = outb + IS;
            __half* p1_h = outb + SS;     __half* p1_l = outb + SS + IS;
            __half* p2_h = outb + 2 * SS; __half* p2_l = outb + 2 * SS + IS;
#pragma unroll
            for (int mi = 0; mi < 2; ++mi)
#pragma unroll
                for (int nj = 0; nj < 8; ++nj) {
                    const int n = nc0 + nj * 8;
#pragma unroll
                    for (int h = 0; h < 2; ++h) {
                        const int m = mr + mi * 16 + h * 8;
                        const size_t o = (size_t)m * HID + n;
                        const float f0 = acc[mi][nj][2*h], f1 = acc[mi][nj][2*h+1];
                        __half h0, l0, h1, l1;
                        if (s == 0) {
                            float a0 = tanhf(f0 + bs[n]);
                            float a1 = tanhf(f1 + bs[n + 1]);
                            split_h(a0, h0, l0); split_h(a1, h1, l1);
                            *(uint32_t*)(pv_h + o) = pack_h(h0, h1);
                            *(uint32_t*)(pv_l + o) = pack_h(l0, l1);
                        } else {
                            const uint32_t uh = *(const uint32_t*)(pv_h + o);
                            const uint32_t ul = *(const uint32_t*)(pv_l + o);
                            const float a0 = h_lo(uh) + h_lo(ul);
                            const float a1 = h_hi(uh) + h_hi(ul);
                            const float s0 = 1.0f - a0 * a0;
                            const float s1 = 1.0f - a1 * a1;
                            if (s == 1) {
                                *(float2*)(g_z1 + o) = make_float2(f0, f1);
                                split_h(s0 * f0, h0, l0);
                                split_h(s1 * f1, h1, l1);
                                *(uint32_t*)(p1_h + o) = pack_h(h0, h1);
                                *(uint32_t*)(p1_l + o) = pack_h(l0, l1);
                            } else {
                                const float2 z1 = *(const float2*)(g_z1 + o);
                                split_h(s0 * (f0 - 2.0f * a0 * z1.x * z1.x), h0, l0);
                                split_h(s1 * (f1 - 2.0f * a1 * z1.y * z1.y), h1, l1);
                                *(uint32_t*)(p2_h + o) = pack_h(h0, h1);
                                *(uint32_t*)(p2_l + o) = pack_h(l0, l1);
                            }
                        }
                    }
                }
        }
    }
}

// ---------------------------------------------------------------------------
__global__ void final_kernel(const float* __restrict__ W4,
                             const float* __restrict__ b4,
                             float* __restrict__ out, int n_eq, int gfin) {
    int tid = threadIdx.x, wid = tid >> 5, lane = tid & 31;
    int pt = blockIdx.x * 8 + wid;
    bool eq = pt < n_eq;
    int s = eq ? 2 : 0;
    int j0 = lane * 8;
    const __half* ph = &g_state[gfin][s][0][0][0] + (size_t)pt * HID + j0;
    const __half* pl = &g_state[gfin][s][1][0][0] + (size_t)pt * HID + j0;
    uint4 uh = *(const uint4*)ph, ul = *(const uint4*)pl;
    const __half* hh = (const __half*)&uh;
    const __half* ll = (const __half*)&ul;
    float sum = 0.0f;
#pragma unroll
    for (int i = 0; i < 8; ++i)
        sum = fmaf(__half2float(hh[i]) + __half2float(ll[i]), W4[j0 + i], sum);
#pragma unroll
    for (int o = 16; o > 0; o >>= 1)
        sum += __shfl_xor_sync(0xffffffffu, sum, o);
    if (lane == 0) out[pt] = sum + (eq ? 0.0f : b4[0]);
}

// ---------------------------------------------------------------------------
extern "C" void kernel_launch(void* const* d_in, const int* in_sizes, int n_in,
                              void* d_out, int out_size)
{
    const float* x_eq = (const float*)d_in[0];
    const float* x_b  = (const float*)d_in[1];
    const float* W0 = (const float*)d_in[2];  const float* b0 = (const float*)d_in[3];
    const float* W1 = (const float*)d_in[4];  const float* b1 = (const float*)d_in[5];
    const float* W2 = (const float*)d_in[6];  const float* b2 = (const float*)d_in[7];
    const float* W3 = (const float*)d_in[8];  const float* b3 = (const float*)d_in[9];
    const float* W4 = (const float*)d_in[10]; const float* b4 = (const float*)d_in[11];
    float* out = (float*)d_out;

    const int n_eq = in_sizes[0];
    const int n_b  = in_sizes[1];
    const int npts = n_eq + n_b;

    cudaFuncSetAttribute(hidden_kernel,
                         cudaFuncAttributeMaxDynamicSharedMemorySize, SMEM_HK);

    prep_kernel<<<3 * HID * HID / 256, 256>>>(W1, W2, W3);
    layer0_kernel<<<npts / 8, 256>>>(x_eq, x_b, W0, b0, n_eq);
    hidden_kernel<<<npts / 64, THD, SMEM_HK>>>(0, 1, 0, b1);
    hidden_kernel<<<npts / 64, THD, SMEM_HK>>>(1, 0, 1, b2);
    hidden_kernel<<<npts / 64, THD, SMEM_HK>>>(0, 1, 2, b3);
    final_kernel<<<npts / 8, 256>>>(W4, b4, out, n_eq, 1);
}

// round 15
// speedup vs baseline: 1.1985x; 1.1985x over previous
#include <cuda_runtime.h>
#include <cuda_fp16.h>
#include <cstdint>

#define HID  256
#define NPTS 270336               // 262144 eq + 8192 boundary

// ---------------------------------------------------------------------------
// Static device scratch
// state[gen][stream v/d1/d2][hi=0,lo=1][pt][k]
__device__ __half g_state[2][3][2][NPTS][HID];
// transposed split weights: wt[layer][img][j][k] = split(W[k][j])
__device__ __half g_wt[3][2][HID][HID];
// z' f32 scratch (written stream-1 epilogue, read stream-2 epilogue by same thread)
__device__ float g_z1[(size_t)NPTS * HID];

// ---------------------------------------------------------------------------
#define SWZ64(o) ((uint32_t)(o) ^ ((((uint32_t)(o)) >> 3) & 0x30))

__device__ __forceinline__ uint32_t smem_u32(const void* p) {
    uint32_t a;
    asm("{ .reg .u64 t; cvta.to.shared.u64 t, %1; cvt.u32.u64 %0, t; }"
        : "=r"(a) : "l"(p));
    return a;
}
__device__ __forceinline__ void ldsm4(uint32_t* r, uint32_t a) {
    asm volatile("ldmatrix.sync.aligned.m8n8.x4.shared.b16 {%0,%1,%2,%3}, [%4];"
                 : "=r"(r[0]), "=r"(r[1]), "=r"(r[2]), "=r"(r[3]) : "r"(a));
}
__device__ __forceinline__ void mma_f16(float* c, const uint32_t* a,
                                        uint32_t b0, uint32_t b1) {
    asm volatile(
        "mma.sync.aligned.m16n8k16.row.col.f32.f16.f16.f32 "
        "{%0,%1,%2,%3}, {%4,%5,%6,%7}, {%8,%9}, {%0,%1,%2,%3};"
        : "+f"(c[0]), "+f"(c[1]), "+f"(c[2]), "+f"(c[3])
        : "r"(a[0]), "r"(a[1]), "r"(a[2]), "r"(a[3]), "r"(b0), "r"(b1));
}
#define CP16(dst, src) \
    asm volatile("cp.async.cg.shared.global [%0], [%1], 16;" \
                 :: "r"(dst), "l"(src) : "memory")
#define CP_COMMIT() asm volatile("cp.async.commit_group;" ::: "memory")
#define CP_WAIT1()  asm volatile("cp.async.wait_group 1;" ::: "memory")
#define CP_WAIT0()  asm volatile("cp.async.wait_group 0;" ::: "memory")

__device__ __forceinline__ void split_h(float v, __half& hi, __half& lo) {
    hi = __float2half_rn(v);
    lo = __float2half_rn(v - __half2float(hi));
}
__device__ __forceinline__ uint32_t pack_h(__half a, __half b) {
    return (uint32_t)__half_as_ushort(a) | ((uint32_t)__half_as_ushort(b) << 16);
}
__device__ __forceinline__ float h_lo(uint32_t u) {
    return __half2float(__ushort_as_half((unsigned short)(u & 0xFFFF)));
}
__device__ __forceinline__ float h_hi(uint32_t u) {
    return __half2float(__ushort_as_half((unsigned short)(u >> 16)));
}

// ---------------------------------------------------------------------------
__global__ void prep_kernel(const float* __restrict__ W1,
                            const float* __restrict__ W2,
                            const float* __restrict__ W3) {
    const float* Ws[3] = {W1, W2, W3};
    int idx = blockIdx.x * 256 + threadIdx.x;   // < 196608
    int l = idx >> 16, r = idx & 0xFFFF;
    int j = r >> 8, k = r & 255;
    __half hi, lo;
    split_h(Ws[l][k * HID + j], hi, lo);
    g_wt[l][0][j][k] = hi;
    g_wt[l][1][j][k] = lo;
}

__global__ void layer0_kernel(const float* __restrict__ xe,
                              const float* __restrict__ xb,
                              const float* __restrict__ W0,
                              const float* __restrict__ b0, int n_eq) {
    int tid = threadIdx.x, wid = tid >> 5, lane = tid & 31;
    int pt = blockIdx.x * 8 + wid;
    bool eq = pt < n_eq;
    float xv = eq ? xe[pt] : xb[pt - n_eq];
    int j0 = lane * 8;
    __half vh[8], vl[8], ah[8], al[8], bh[8], bl[8];
#pragma unroll
    for (int i = 0; i < 8; ++i) {
        float w = W0[j0 + i];
        float z = fmaf(xv, w, b0[j0 + i]);
        float a = tanhf(z);
        float sf = 1.0f - a * a;
        float d1 = eq ? sf * w : 0.0f;
        float d2 = eq ? (-2.0f * a * sf * w * w) : 0.0f;
        split_h(a,  vh[i], vl[i]);
        split_h(d1, ah[i], al[i]);
        split_h(d2, bh[i], bl[i]);
    }
    size_t off = (size_t)pt * HID + j0;
    *(uint4*)(&g_state[0][0][0][0][0] + off) = *(uint4*)vh;
    *(uint4*)(&g_state[0][0][1][0][0] + off) = *(uint4*)vl;
    *(uint4*)(&g_state[0][1][0][0][0] + off) = *(uint4*)ah;
    *(uint4*)(&g_state[0][1][1][0][0] + off) = *(uint4*)al;
    *(uint4*)(&g_state[0][2][0][0][0] + off) = *(uint4*)bh;
    *(uint4*)(&g_state[0][2][1][0][0] + off) = *(uint4*)bl;
}

// ---------------------------------------------------------------------------
// hidden layer: CTA = 128 pts x 128 N (blockIdx.y = N-half), 256 threads,
// 8 warps in 2(m) x 4(n), warp tile 64x32, 2 CTAs/SM.
// kc=32, 24 iters, 3 buffers, depth-2 cp.async, 1 barrier/chunk.
// Buffer: A 2img x [128][32] (16KB) + B 2img x [128][32] (16KB) = 32KB.
// A-frag regs reused: (ah·bh, ah·bl) then A-lo overwrites for (al·bh).
// ---------------------------------------------------------------------------
#define BUFB       32768
#define SM_buf(b)  ((b) * BUFB)
#define SM_BIAS    98304
#define SMEM_HK    99328
#define NITER      24
#define THD        256

__global__ void __launch_bounds__(THD, 2)
hidden_kernel(int gin, int gout, int lw, const float* __restrict__ bias)
{
    extern __shared__ char sm[];
    const uint32_t sb = smem_u32(sm);
    float* bs = (float*)(sm + SM_BIAS);
    const int tid = threadIdx.x, lane = tid & 31, wid = tid >> 5;
    const int wm = wid >> 2, wn = wid & 3;        // warp grid 2(m) x 4(n)
    const int pt0 = blockIdx.x * 128;
    const int nh  = blockIdx.y;                   // N-half 0/1

    bs[tid] = bias[tid];

    const __half* wbase = &g_wt[lw][0][0][0];
    const __half* sbase = &g_state[gin][0][0][0][0];
    __half* outb = &g_state[gout][0][0][0][0];
    const size_t IS = (size_t)NPTS * HID;         // img stride
    const size_t SS = 2 * IS;                     // stream stride

    // ---- thread-constant staging offsets ----
    // A: 1024 16B-units (2 img x 128 rows x 4), B: 1024 (2 img x 128 rows x 4)
    uint32_t a_dst[4]; size_t a_src[4];
    uint32_t b_dst[4]; size_t b_src[4];
#pragma unroll
    for (int i = 0; i < 4; ++i) {
        int idx = tid + i * THD;
        int img = idx >> 9, u = idx & 511, row = u >> 2, k8 = u & 3;
        a_dst[i] = img * 8192 + SWZ64(row * 64 + k8 * 16);
        a_src[i] = (size_t)img * IS + (size_t)(pt0 + row) * HID + k8 * 8;
        b_dst[i] = 16384 + img * 8192 + SWZ64(row * 64 + k8 * 16);
        b_src[i] = (size_t)img * HID * HID + (size_t)(nh * 128 + row) * HID + k8 * 8;
    }

    auto stage = [&](int it) {
        const int s = it >> 3, c = it & 7;
        const __half* ab = sbase + (size_t)s * SS + c * 32;
        const __half* bb = wbase + c * 32;
        const uint32_t buf = sb + SM_buf(it % 3);
#pragma unroll
        for (int i = 0; i < 4; ++i) CP16(buf + a_dst[i], ab + a_src[i]);
#pragma unroll
        for (int i = 0; i < 4; ++i) CP16(buf + b_dst[i], bb + b_src[i]);
        CP_COMMIT();
    };

    float acc[4][4][4];
    stage(0);
    stage(1);

    // ---- hoisted ldsm offsets, full swizzle per (row, kk) — exact ----
    const uint32_t klane = (lane >> 4) << 4;
    const int rA = wm * 64 + (lane & 15);
    const int rB = wn * 32 + (lane & 15);
    uint32_t aoff[4][2], boff[2][2];
#pragma unroll
    for (int mi = 0; mi < 4; ++mi)
#pragma unroll
        for (int kk = 0; kk < 2; ++kk)
            aoff[mi][kk] = SWZ64((uint32_t)((rA + mi * 16) * 64) + klane + kk * 32);
#pragma unroll
    for (int g = 0; g < 2; ++g)
#pragma unroll
        for (int kk = 0; kk < 2; ++kk)
            boff[g][kk] = SWZ64((uint32_t)((rB + g * 16) * 64) + klane + kk * 32);

    for (int it = 0; it < NITER; ++it) {
        const int s = it >> 3, c = it & 7;

        if (c == 0) {
#pragma unroll
            for (int mi = 0; mi < 4; ++mi)
#pragma unroll
                for (int nj = 0; nj < 4; ++nj)
#pragma unroll
                    for (int q = 0; q < 4; ++q) acc[mi][nj][q] = 0.0f;
        }

        if (it + 2 < NITER) CP_WAIT1();
        else                CP_WAIT0();
        __syncthreads();                 // chunk(it) visible; compute(it-1) done
        if (it + 2 < NITER) stage(it + 2);

        const uint32_t abuf = sb + SM_buf(it % 3);
        const uint32_t bbuf = abuf + 16384;
#pragma unroll
        for (int kk = 0; kk < 2; ++kk) {
            uint32_t af[4][4], bh[2][4], bl[2][4];
            // A-hi + both B imgs
#pragma unroll
            for (int mi = 0; mi < 4; ++mi) ldsm4(af[mi], abuf + aoff[mi][kk]);
#pragma unroll
            for (int g = 0; g < 2; ++g) {
                ldsm4(bh[g], bbuf + boff[g][kk]);
                ldsm4(bl[g], bbuf + 8192 + boff[g][kk]);
            }
            // pass ah·bh
#pragma unroll
            for (int mi = 0; mi < 4; ++mi)
#pragma unroll
                for (int g = 0; g < 2; ++g) {
                    mma_f16(acc[mi][2*g],   af[mi], bh[g][0], bh[g][2]);
                    mma_f16(acc[mi][2*g+1], af[mi], bh[g][1], bh[g][3]);
                }
            // pass ah·bl
#pragma unroll
            for (int mi = 0; mi < 4; ++mi)
#pragma unroll
                for (int g = 0; g < 2; ++g) {
                    mma_f16(acc[mi][2*g],   af[mi], bl[g][0], bl[g][2]);
                    mma_f16(acc[mi][2*g+1], af[mi], bl[g][1], bl[g][3]);
                }
            // A-lo overwrites A-hi regs; pass al·bh
#pragma unroll
            for (int mi = 0; mi < 4; ++mi) ldsm4(af[mi], abuf + 8192 + aoff[mi][kk]);
#pragma unroll
            for (int mi = 0; mi < 4; ++mi)
#pragma unroll
                for (int g = 0; g < 2; ++g) {
                    mma_f16(acc[mi][2*g],   af[mi], bh[g][0], bh[g][2]);
                    mma_f16(acc[mi][2*g+1], af[mi], bh[g][1], bh[g][3]);
                }
        }

        if (c == 7) {
            // ---- epilogue: c frag rows lane>>2 +{0,8}; cols (lane&3)*2 +{0,1} ----
            const int mr  = pt0 + wm * 64 + (lane >> 2);
            const int nc0 = nh * 128 + wn * 32 + (lane & 3) * 2;
            __half* pv_h = outb;          __half* pv_l = outb + IS;
            __half* p1_h = outb + SS;     __half* p1_l = outb + SS + IS;
            __half* p2_h = outb + 2 * SS; __half* p2_l = outb + 2 * SS + IS;
#pragma unroll
            for (int mi = 0; mi < 4; ++mi)
#pragma unroll
                for (int nj = 0; nj < 4; ++nj) {
                    const int n = nc0 + nj * 8;
#pragma unroll
                    for (int h = 0; h < 2; ++h) {
                        const int m = mr + mi * 16 + h * 8;
                        const size_t o = (size_t)m * HID + n;
                        const float f0 = acc[mi][nj][2*h], f1 = acc[mi][nj][2*h+1];
                        __half h0, l0, h1, l1;
                        if (s == 0) {
                            float a0 = tanhf(f0 + bs[n]);
                            float a1 = tanhf(f1 + bs[n + 1]);
                            split_h(a0, h0, l0); split_h(a1, h1, l1);
                            *(uint32_t*)(pv_h + o) = pack_h(h0, h1);
                            *(uint32_t*)(pv_l + o) = pack_h(l0, l1);
                        } else {
                            const uint32_t uh = *(const uint32_t*)(pv_h + o);
                            const uint32_t ul = *(const uint32_t*)(pv_l + o);
                            const float a0 = h_lo(uh) + h_lo(ul);
                            const float a1 = h_hi(uh) + h_hi(ul);
                            const float s0 = 1.0f - a0 * a0;
                            const float s1 = 1.0f - a1 * a1;
                            if (s == 1) {
                                *(float2*)(g_z1 + o) = make_float2(f0, f1);
                                split_h(s0 * f0, h0, l0);
                                split_h(s1 * f1, h1, l1);
                                *(uint32_t*)(p1_h + o) = pack_h(h0, h1);
                                *(uint32_t*)(p1_l + o) = pack_h(l0, l1);
                            } else {
                                const float2 z1 = *(const float2*)(g_z1 + o);
                                split_h(s0 * (f0 - 2.0f * a0 * z1.x * z1.x), h0, l0);
                                split_h(s1 * (f1 - 2.0f * a1 * z1.y * z1.y), h1, l1);
                                *(uint32_t*)(p2_h + o) = pack_h(h0, h1);
                                *(uint32_t*)(p2_l + o) = pack_h(l0, l1);
                            }
                        }
                    }
                }
        }
    }
}

// ---------------------------------------------------------------------------
__global__ void final_kernel(const float* __restrict__ W4,
                             const float* __restrict__ b4,
                             float* __restrict__ out, int n_eq, int gfin) {
    int tid = threadIdx.x, wid = tid >> 5, lane = tid & 31;
    int pt = blockIdx.x * 8 + wid;
    bool eq = pt < n_eq;
    int s = eq ? 2 : 0;
    int j0 = lane * 8;
    const __half* ph = &g_state[gfin][s][0][0][0] + (size_t)pt * HID + j0;
    const __half* pl = &g_state[gfin][s][1][0][0] + (size_t)pt * HID + j0;
    uint4 uh = *(const uint4*)ph, ul = *(const uint4*)pl;
    const __half* hh = (const __half*)&uh;
    const __half* ll = (const __half*)&ul;
    float sum = 0.0f;
#pragma unroll
    for (int i = 0; i < 8; ++i)
        sum = fmaf(__half2float(hh[i]) + __half2float(ll[i]), W4[j0 + i], sum);
#pragma unroll
    for (int o = 16; o > 0; o >>= 1)
        sum += __shfl_xor_sync(0xffffffffu, sum, o);
    if (lane == 0) out[pt] = sum + (eq ? 0.0f : b4[0]);
}

// ---------------------------------------------------------------------------
extern "C" void kernel_launch(void* const* d_in, const int* in_sizes, int n_in,
                              void* d_out, int out_size)
{
    const float* x_eq = (const float*)d_in[0];
    const float* x_b  = (const float*)d_in[1];
    const float* W0 = (const float*)d_in[2];  const float* b0 = (const float*)d_in[3];
    const float* W1 = (const float*)d_in[4];  const float* b1 = (const float*)d_in[5];
    const float* W2 = (const float*)d_in[6];  const float* b2 = (const float*)d_in[7];
    const float* W3 = (const float*)d_in[8];  const float* b3 = (const float*)d_in[9];
    const float* W4 = (const float*)d_in[10]; const float* b4 = (const float*)d_in[11];
    float* out = (float*)d_out;

    const int n_eq = in_sizes[0];
    const int n_b  = in_sizes[1];
    const int npts = n_eq + n_b;

    cudaFuncSetAttribute(hidden_kernel,
                         cudaFuncAttributeMaxDynamicSharedMemorySize, SMEM_HK);

    dim3 grid(npts / 128, 2);
    prep_kernel<<<3 * HID * HID / 256, 256>>>(W1, W2, W3);
    layer0_kernel<<<npts / 8, 256>>>(x_eq, x_b, W0, b0, n_eq);
    hidden_kernel<<<grid, THD, SMEM_HK>>>(0, 1, 0, b1);
    hidden_kernel<<<grid, THD, SMEM_HK>>>(1, 0, 1, b2);
    hidden_kernel<<<grid, THD, SMEM_HK>>>(0, 1, 2, b3);
    final_kernel<<<npts / 8, 256>>>(W4, b4, out, n_eq, 1);
}

// round 16
// speedup vs baseline: 1.2236x; 1.0210x over previous
#include <cuda_runtime.h>
#include <cuda_fp16.h>
#include <cstdint>

#define HID  256
#define NPTS 270336               // 262144 eq + 8192 boundary

// ---------------------------------------------------------------------------
// Static device scratch
// state[gen][stream v/d1/d2][hi=0,lo=1][pt][k]
__device__ __half g_state[2][3][2][NPTS][HID];
// transposed split weights: wt[layer][img][j][k] = split(W[k][j])
__device__ __half g_wt[3][2][HID][HID];
// z' f32 scratch (written stream-1 epilogue, read stream-2 epilogue by same thread)
__device__ float g_z1[(size_t)NPTS * HID];

// ---------------------------------------------------------------------------
#define SWZ64(o) ((uint32_t)(o) ^ ((((uint32_t)(o)) >> 3) & 0x30))

__device__ __forceinline__ uint32_t smem_u32(const void* p) {
    uint32_t a;
    asm("{ .reg .u64 t; cvta.to.shared.u64 t, %1; cvt.u32.u64 %0, t; }"
        : "=r"(a) : "l"(p));
    return a;
}
__device__ __forceinline__ void ldsm4(uint32_t* r, uint32_t a) {
    asm volatile("ldmatrix.sync.aligned.m8n8.x4.shared.b16 {%0,%1,%2,%3}, [%4];"
                 : "=r"(r[0]), "=r"(r[1]), "=r"(r[2]), "=r"(r[3]) : "r"(a));
}
__device__ __forceinline__ void mma_f16(float* c, const uint32_t* a,
                                        uint32_t b0, uint32_t b1) {
    asm volatile(
        "mma.sync.aligned.m16n8k16.row.col.f32.f16.f16.f32 "
        "{%0,%1,%2,%3}, {%4,%5,%6,%7}, {%8,%9}, {%0,%1,%2,%3};"
        : "+f"(c[0]), "+f"(c[1]), "+f"(c[2]), "+f"(c[3])
        : "r"(a[0]), "r"(a[1]), "r"(a[2]), "r"(a[3]), "r"(b0), "r"(b1));
}
#define CP16(dst, src) \
    asm volatile("cp.async.cg.shared.global [%0], [%1], 16;" \
                 :: "r"(dst), "l"(src) : "memory")
#define CP_COMMIT() asm volatile("cp.async.commit_group;" ::: "memory")
#define CP_WAIT1()  asm volatile("cp.async.wait_group 1;" ::: "memory")
#define CP_WAIT0()  asm volatile("cp.async.wait_group 0;" ::: "memory")

__device__ __forceinline__ void split_h(float v, __half& hi, __half& lo) {
    hi = __float2half_rn(v);
    lo = __float2half_rn(v - __half2float(hi));
}
__device__ __forceinline__ uint32_t pack_h(__half a, __half b) {
    return (uint32_t)__half_as_ushort(a) | ((uint32_t)__half_as_ushort(b) << 16);
}
__device__ __forceinline__ float h_lo(uint32_t u) {
    return __half2float(__ushort_as_half((unsigned short)(u & 0xFFFF)));
}
__device__ __forceinline__ float h_hi(uint32_t u) {
    return __half2float(__ushort_as_half((unsigned short)(u >> 16)));
}

// ---------------------------------------------------------------------------
__global__ void prep_kernel(const float* __restrict__ W1,
                            const float* __restrict__ W2,
                            const float* __restrict__ W3) {
    const float* Ws[3] = {W1, W2, W3};
    int idx = blockIdx.x * 256 + threadIdx.x;   // < 196608
    int l = idx >> 16, r = idx & 0xFFFF;
    int j = r >> 8, k = r & 255;
    __half hi, lo;
    split_h(Ws[l][k * HID + j], hi, lo);
    g_wt[l][0][j][k] = hi;
    g_wt[l][1][j][k] = lo;
}

__global__ void layer0_kernel(const float* __restrict__ xe,
                              const float* __restrict__ xb,
                              const float* __restrict__ W0,
                              const float* __restrict__ b0, int n_eq) {
    int tid = threadIdx.x, wid = tid >> 5, lane = tid & 31;
    int pt = blockIdx.x * 8 + wid;
    bool eq = pt < n_eq;
    float xv = eq ? xe[pt] : xb[pt - n_eq];
    int j0 = lane * 8;
    __half vh[8], vl[8], ah[8], al[8], bh[8], bl[8];
#pragma unroll
    for (int i = 0; i < 8; ++i) {
        float w = W0[j0 + i];
        float z = fmaf(xv, w, b0[j0 + i]);
        float a = tanhf(z);
        float sf = 1.0f - a * a;
        float d1 = eq ? sf * w : 0.0f;
        float d2 = eq ? (-2.0f * a * sf * w * w) : 0.0f;
        split_h(a,  vh[i], vl[i]);
        split_h(d1, ah[i], al[i]);
        split_h(d2, bh[i], bl[i]);
    }
    size_t off = (size_t)pt * HID + j0;
    *(uint4*)(&g_state[0][0][0][0][0] + off) = *(uint4*)vh;
    *(uint4*)(&g_state[0][0][1][0][0] + off) = *(uint4*)vl;
    *(uint4*)(&g_state[0][1][0][0][0] + off) = *(uint4*)ah;
    *(uint4*)(&g_state[0][1][1][0][0] + off) = *(uint4*)al;
    *(uint4*)(&g_state[0][2][0][0][0] + off) = *(uint4*)bh;
    *(uint4*)(&g_state[0][2][1][0][0] + off) = *(uint4*)bl;
}

// ---------------------------------------------------------------------------
// hidden layer: CTA = 128 pts x 128 N (blockIdx.y = N-half), 256 threads,
// 8 warps in 2(m) x 4(n), warp tile 64x32, 2 CTAs/SM.
// kc=32, 24 iters FULLY UNROLLED (all it-derived addressing constant),
// 3 buffers, depth-2 cp.async, 1 barrier/chunk.
// ---------------------------------------------------------------------------
#define BUFB       32768
#define SM_buf(b)  ((b) * BUFB)
#define SM_BIAS    98304
#define SMEM_HK    99328
#define NITER      24
#define THD        256

__global__ void __launch_bounds__(THD, 2)
hidden_kernel(int gin, int gout, int lw, const float* __restrict__ bias)
{
    extern __shared__ char sm[];
    const uint32_t sb = smem_u32(sm);
    float* bs = (float*)(sm + SM_BIAS);
    const int tid = threadIdx.x, lane = tid & 31, wid = tid >> 5;
    const int wm = wid >> 2, wn = wid & 3;        // warp grid 2(m) x 4(n)
    const int pt0 = blockIdx.x * 128;
    const int nh  = blockIdx.y;                   // N-half 0/1

    bs[tid] = bias[tid];

    const __half* wbase = &g_wt[lw][0][0][0];
    const __half* sbase = &g_state[gin][0][0][0][0];
    __half* outb = &g_state[gout][0][0][0][0];
    const size_t IS = (size_t)NPTS * HID;         // img stride
    const size_t SS = 2 * IS;                     // stream stride

    // ---- thread-constant staging offsets ----
    uint32_t a_dst[4]; size_t a_src[4];
    uint32_t b_dst[4]; size_t b_src[4];
#pragma unroll
    for (int i = 0; i < 4; ++i) {
        int idx = tid + i * THD;
        int img = idx >> 9, u = idx & 511, row = u >> 2, k8 = u & 3;
        a_dst[i] = img * 8192 + SWZ64(row * 64 + k8 * 16);
        a_src[i] = (size_t)img * IS + (size_t)(pt0 + row) * HID + k8 * 8;
        b_dst[i] = 16384 + img * 8192 + SWZ64(row * 64 + k8 * 16);
        b_src[i] = (size_t)img * HID * HID + (size_t)(nh * 128 + row) * HID + k8 * 8;
    }

    auto stage = [&](int it) {
        const int s = it >> 3, c = it & 7;
        const __half* ab = sbase + (size_t)s * SS + c * 32;
        const __half* bb = wbase + c * 32;
        const uint32_t buf = sb + SM_buf(it % 3);
#pragma unroll
        for (int i = 0; i < 4; ++i) CP16(buf + a_dst[i], ab + a_src[i]);
#pragma unroll
        for (int i = 0; i < 4; ++i) CP16(buf + b_dst[i], bb + b_src[i]);
        CP_COMMIT();
    };

    float acc[4][4][4];
    stage(0);
    stage(1);

    // ---- hoisted ldsm offsets, full swizzle per (row, kk) — exact ----
    const uint32_t klane = (lane >> 4) << 4;
    const int rA = wm * 64 + (lane & 15);
    const int rB = wn * 32 + (lane & 15);
    uint32_t aoff[4][2], boff[2][2];
#pragma unroll
    for (int mi = 0; mi < 4; ++mi)
#pragma unroll
        for (int kk = 0; kk < 2; ++kk)
            aoff[mi][kk] = SWZ64((uint32_t)((rA + mi * 16) * 64) + klane + kk * 32);
#pragma unroll
    for (int g = 0; g < 2; ++g)
#pragma unroll
        for (int kk = 0; kk < 2; ++kk)
            boff[g][kk] = SWZ64((uint32_t)((rB + g * 16) * 64) + klane + kk * 32);

#pragma unroll
    for (int it = 0; it < NITER; ++it) {
        const int s = it >> 3, c = it & 7;

        if (c == 0) {
#pragma unroll
            for (int mi = 0; mi < 4; ++mi)
#pragma unroll
                for (int nj = 0; nj < 4; ++nj)
#pragma unroll
                    for (int q = 0; q < 4; ++q) acc[mi][nj][q] = 0.0f;
        }

        if (it + 2 < NITER) CP_WAIT1();
        else                CP_WAIT0();
        __syncthreads();                 // chunk(it) visible; compute(it-1) done
        if (it + 2 < NITER) stage(it + 2);

        const uint32_t abuf = sb + SM_buf(it % 3);
        const uint32_t bbuf = abuf + 16384;
#pragma unroll
        for (int kk = 0; kk < 2; ++kk) {
            uint32_t af[4][4], bh[2][4], bl[2][4];
#pragma unroll
            for (int mi = 0; mi < 4; ++mi) ldsm4(af[mi], abuf + aoff[mi][kk]);
#pragma unroll
            for (int g = 0; g < 2; ++g) {
                ldsm4(bh[g], bbuf + boff[g][kk]);
                ldsm4(bl[g], bbuf + 8192 + boff[g][kk]);
            }
            // pass ah·bh
#pragma unroll
            for (int mi = 0; mi < 4; ++mi)
#pragma unroll
                for (int g = 0; g < 2; ++g) {
                    mma_f16(acc[mi][2*g],   af[mi], bh[g][0], bh[g][2]);
                    mma_f16(acc[mi][2*g+1], af[mi], bh[g][1], bh[g][3]);
                }
            // pass ah·bl
#pragma unroll
            for (int mi = 0; mi < 4; ++mi)
#pragma unroll
                for (int g = 0; g < 2; ++g) {
                    mma_f16(acc[mi][2*g],   af[mi], bl[g][0], bl[g][2]);
                    mma_f16(acc[mi][2*g+1], af[mi], bl[g][1], bl[g][3]);
                }
            // A-lo overwrites A-hi regs; pass al·bh
#pragma unroll
            for (int mi = 0; mi < 4; ++mi) ldsm4(af[mi], abuf + 8192 + aoff[mi][kk]);
#pragma unroll
            for (int mi = 0; mi < 4; ++mi)
#pragma unroll
                for (int g = 0; g < 2; ++g) {
                    mma_f16(acc[mi][2*g],   af[mi], bh[g][0], bh[g][2]);
                    mma_f16(acc[mi][2*g+1], af[mi], bh[g][1], bh[g][3]);
                }
        }

        if (c == 7) {
            // ---- epilogue: c frag rows lane>>2 +{0,8}; cols (lane&3)*2 +{0,1} ----
            const int mr  = pt0 + wm * 64 + (lane >> 2);
            const int nc0 = nh * 128 + wn * 32 + (lane & 3) * 2;
            __half* pv_h = outb;          __half* pv_l = outb + IS;
            __half* p1_h = outb + SS;     __half* p1_l = outb + SS + IS;
            __half* p2_h = outb + 2 * SS; __half* p2_l = outb + 2 * SS + IS;
#pragma unroll
            for (int mi = 0; mi < 4; ++mi)
#pragma unroll
                for (int nj = 0; nj < 4; ++nj) {
                    const int n = nc0 + nj * 8;
#pragma unroll
                    for (int h = 0; h < 2; ++h) {
                        const int m = mr + mi * 16 + h * 8;
                        const size_t o = (size_t)m * HID + n;
                        const float f0 = acc[mi][nj][2*h], f1 = acc[mi][nj][2*h+1];
                        __half h0, l0, h1, l1;
                        if (s == 0) {
                            float a0 = tanhf(f0 + bs[n]);
                            float a1 = tanhf(f1 + bs[n + 1]);
                            split_h(a0, h0, l0); split_h(a1, h1, l1);
                            *(uint32_t*)(pv_h + o) = pack_h(h0, h1);
                            *(uint32_t*)(pv_l + o) = pack_h(l0, l1);
                        } else {
                            const uint32_t uh = *(const uint32_t*)(pv_h + o);
                            const uint32_t ul = *(const uint32_t*)(pv_l + o);
                            const float a0 = h_lo(uh) + h_lo(ul);
                            const float a1 = h_hi(uh) + h_hi(ul);
                            const float s0 = 1.0f - a0 * a0;
                            const float s1 = 1.0f - a1 * a1;
                            if (s == 1) {
                                *(float2*)(g_z1 + o) = make_float2(f0, f1);
                                split_h(s0 * f0, h0, l0);
                                split_h(s1 * f1, h1, l1);
                                *(uint32_t*)(p1_h + o) = pack_h(h0, h1);
                                *(uint32_t*)(p1_l + o) = pack_h(l0, l1);
                            } else {
                                const float2 z1 = *(const float2*)(g_z1 + o);
                                split_h(s0 * (f0 - 2.0f * a0 * z1.x * z1.x), h0, l0);
                                split_h(s1 * (f1 - 2.0f * a1 * z1.y * z1.y), h1, l1);
                                *(uint32_t*)(p2_h + o) = pack_h(h0, h1);
                                *(uint32_t*)(p2_l + o) = pack_h(l0, l1);
                            }
                        }
                    }
                }
        }
    }
}

// ---------------------------------------------------------------------------
__global__ void final_kernel(const float* __restrict__ W4,
                             const float* __restrict__ b4,
                             float* __restrict__ out, int n_eq, int gfin) {
    int tid = threadIdx.x, wid = tid >> 5, lane = tid & 31;
    int pt = blockIdx.x * 8 + wid;
    bool eq = pt < n_eq;
    int s = eq ? 2 : 0;
    int j0 = lane * 8;
    const __half* ph = &g_state[gfin][s][0][0][0] + (size_t)pt * HID + j0;
    const __half* pl = &g_state[gfin][s][1][0][0] + (size_t)pt * HID + j0;
    uint4 uh = *(const uint4*)ph, ul = *(const uint4*)pl;
    const __half* hh = (const __half*)&uh;
    const __half* ll = (const __half*)&ul;
    float sum = 0.0f;
#pragma unroll
    for (int i = 0; i < 8; ++i)
        sum = fmaf(__half2float(hh[i]) + __half2float(ll[i]), W4[j0 + i], sum);
#pragma unroll
    for (int o = 16; o > 0; o >>= 1)
        sum += __shfl_xor_sync(0xffffffffu, sum, o);
    if (lane == 0) out[pt] = sum + (eq ? 0.0f : b4[0]);
}

// ---------------------------------------------------------------------------
extern "C" void kernel_launch(void* const* d_in, const int* in_sizes, int n_in,
                              void* d_out, int out_size)
{
    const float* x_eq = (const float*)d_in[0];
    const float* x_b  = (const float*)d_in[1];
    const float* W0 = (const float*)d_in[2];  const float* b0 = (const float*)d_in[3];
    const float* W1 = (const float*)d_in[4];  const float* b1 = (const float*)d_in[5];
    const float* W2 = (const float*)d_in[6];  const float* b2 = (const float*)d_in[7];
    const float* W3 = (const float*)d_in[8];  const float* b3 = (const float*)d_in[9];
    const float* W4 = (const float*)d_in[10]; const float* b4 = (const float*)d_in[11];
    float* out = (float*)d_out;

    const int n_eq = in_sizes[0];
    const int n_b  = in_sizes[1];
    const int npts = n_eq + n_b;

    cudaFuncSetAttribute(hidden_kernel,
                         cudaFuncAttributeMaxDynamicSharedMemorySize, SMEM_HK);

    dim3 grid(npts / 128, 2);
    prep_kernel<<<3 * HID * HID / 256, 256>>>(W1, W2, W3);
    layer0_kernel<<<npts / 8, 256>>>(x_eq, x_b, W0, b0, n_eq);
    hidden_kernel<<<grid, THD, SMEM_HK>>>(0, 1, 0, b1);
    hidden_kernel<<<grid, THD, SMEM_HK>>>(1, 0, 1, b2);
    hidden_kernel<<<grid, THD, SMEM_HK>>>(0, 1, 2, b3);
    final_kernel<<<npts / 8, 256>>>(W4, b4, out, n_eq, 1);
}